// round 14
// baseline (speedup 1.0000x reference)
#include <cuda_runtime.h>
#include <math.h>
#include <stdint.h>

#define S_LEN 2048
#define BATCH 2
#define DMODEL 1024
#define NHEAD 16
#define HDK 64
#define NROWS (S_LEN * BATCH)   // 4096

// Scratch (allocation-free rule: __device__ globals)
__device__ float g_q[NROWS * DMODEL];
__device__ float g_k[NROWS * DMODEL];
__device__ float g_v[NROWS * DMODEL];
__device__ float g_ctx[NROWS * DMODEL];
__device__ float g_cos[S_LEN * HDK];
__device__ float g_sin[S_LEN * HDK];

// ---------------------------------------------------------------------------
// RoPE table: cos/sin(pos * invf[d & 31]); matches reference exactly.
// ---------------------------------------------------------------------------
__global__ void rope_table_kernel(float* __restrict__ cosT, float* __restrict__ sinT)
{
    const int idx = blockIdx.x * blockDim.x + threadIdx.x;   // S_LEN*64
    const int s = idx >> 6;
    const int d = idx & 63;
    const int j = d & 31;
    const float invf = 1.0f / powf(10000.0f, (float)(2 * j) * (1.0f / 64.0f));
    float sv, cv;
    sincosf((float)s * invf, &sv, &cv);
    cosT[idx] = cv;
    sinT[idx] = sv;
}

// ---------------------------------------------------------------------------
// tf32 helpers (3xTF32 split: x = hi + lo, residual ~2^-21)
// ---------------------------------------------------------------------------
__device__ __forceinline__ uint32_t f2tf32(float x) {
    uint32_t r;
    asm("cvt.rna.tf32.f32 %0, %1;" : "=r"(r) : "f"(x));
    return r;
}

__device__ __forceinline__ void mma8(float* d, const uint32_t* a, const uint32_t* b) {
    asm("mma.sync.aligned.m16n8k8.row.col.f32.tf32.tf32.f32 "
        "{%0,%1,%2,%3}, {%4,%5,%6,%7}, {%8,%9}, {%0,%1,%2,%3};"
        : "+f"(d[0]), "+f"(d[1]), "+f"(d[2]), "+f"(d[3])
        : "r"(a[0]), "r"(a[1]), "r"(a[2]), "r"(a[3]), "r"(b[0]), "r"(b[1]));
}

__device__ __forceinline__ void split3(float x, uint32_t& hi, uint32_t& lo) {
    hi = f2tf32(x);
    lo = f2tf32(x - __uint_as_float(hi));
}

// ---------------------------------------------------------------------------
// Tensor-core projection GEMM v3.2: pre-split hi/lo smem planes, double-
// buffered (67.6 KB dynamic smem, one __syncthreads per BK step).
// __launch_bounds__(256, 1): ~140 live regs force 1 CTA/SM anyway.
// Epilogue bias hoisted to 4x float2 register loads (was 64 scalar LDG).
// 128x128 tile, BK=16, 8 warps (2x4), warp tile 64x32, 3xTF32.
// ---------------------------------------------------------------------------
#define SSTR 132
#define PPLANE (16 * SSTR)              // one [16][SSTR] plane, u32 words
#define PBUF   (4 * PPLANE)             // AsH,AsL,WsH,WsL
#define PROJ_SMEM_BYTES (2 * PBUF * 4)  // 67,584 B

__global__ __launch_bounds__(256, 1) void proj_kernel(
    const float* __restrict__ X0, const float* __restrict__ X1, const float* __restrict__ X2,
    const float* __restrict__ W0, const float* __restrict__ W1, const float* __restrict__ W2,
    const float* __restrict__ B0, const float* __restrict__ B1, const float* __restrict__ B2,
    float* __restrict__ O0, float* __restrict__ O1, float* __restrict__ O2,
    const float* __restrict__ cosT, const float* __restrict__ sinT,
    int rope_mask, int head_layout)
{
    extern __shared__ uint32_t psm[];

    const int z = blockIdx.z;
    const float* X = (z == 0) ? X0 : (z == 1) ? X1 : X2;
    const float* W = (z == 0) ? W0 : (z == 1) ? W1 : W2;
    const float* bias = (z == 0) ? B0 : (z == 1) ? B1 : B2;
    float* out = (z == 0) ? O0 : (z == 1) ? O1 : O2;
    const int rope = (rope_mask >> z) & 1;

    const int tid = threadIdx.x;
    const int lane = tid & 31;
    const int warp = tid >> 5;
    const int gid = lane >> 2;
    const int tig = lane & 3;
    const int wm = warp >> 2;
    const int wn = warp & 3;

    const int rowBase = blockIdx.y * 128;
    const int colBase = blockIdx.x * 128;

    const int ldRow = tid & 127;
    const int ldKg  = (tid >> 7) * 8;

    const float* xp = &X[(long)(rowBase + ldRow) * DMODEL + ldKg];
    const float* wp = &W[(long)(colBase + ldRow) * DMODEL + ldKg];

    float acc[4][4][4] = {};

    // Prologue: tile 0 split-stored to buffer 0
    {
        uint32_t* AsH = psm;
        uint32_t* AsL = psm + PPLANE;
        uint32_t* WsH = psm + 2 * PPLANE;
        uint32_t* WsL = psm + 3 * PPLANE;
        float4 a0 = *reinterpret_cast<const float4*>(xp);
        float4 a1 = *reinterpret_cast<const float4*>(xp + 4);
        float4 w0 = *reinterpret_cast<const float4*>(wp);
        float4 w1 = *reinterpret_cast<const float4*>(wp + 4);
        const float av[8] = {a0.x, a0.y, a0.z, a0.w, a1.x, a1.y, a1.z, a1.w};
        const float wv[8] = {w0.x, w0.y, w0.z, w0.w, w1.x, w1.y, w1.z, w1.w};
        #pragma unroll
        for (int j = 0; j < 8; j++) {
            uint32_t h_, l_;
            split3(av[j], h_, l_);
            AsH[(ldKg + j) * SSTR + ldRow] = h_; AsL[(ldKg + j) * SSTR + ldRow] = l_;
            split3(wv[j], h_, l_);
            WsH[(ldKg + j) * SSTR + ldRow] = h_; WsL[(ldKg + j) * SSTR + ldRow] = l_;
        }
    }
    __syncthreads();

    int buf = 0;
    #pragma unroll 1
    for (int k0 = 16; k0 <= DMODEL; k0 += 16) {
        const int has_next = (k0 < DMODEL);
        float4 pa0, pa1, pw0, pw1;
        if (has_next) {
            pa0 = *reinterpret_cast<const float4*>(xp + k0);
            pa1 = *reinterpret_cast<const float4*>(xp + k0 + 4);
            pw0 = *reinterpret_cast<const float4*>(wp + k0);
            pw1 = *reinterpret_cast<const float4*>(wp + k0 + 4);
        }

        const uint32_t* AsH = psm + buf * PBUF;
        const uint32_t* AsL = AsH + PPLANE;
        const uint32_t* WsH = AsH + 2 * PPLANE;
        const uint32_t* WsL = AsH + 3 * PPLANE;

        #pragma unroll
        for (int kc = 0; kc < 16; kc += 8) {
            uint32_t Ahi[4][4], Alo[4][4], Bhi[4][2], Blo[4][2];

            #pragma unroll
            for (int mi = 0; mi < 4; mi++) {
                const int r = wm * 64 + mi * 16 + gid;
                #pragma unroll
                for (int q = 0; q < 4; q++) {
                    const int kk = kc + tig + ((q >> 1) << 2);
                    const int rr = r + ((q & 1) << 3);
                    Ahi[mi][q] = AsH[kk * SSTR + rr];
                    Alo[mi][q] = AsL[kk * SSTR + rr];
                }
            }
            #pragma unroll
            for (int ni = 0; ni < 4; ni++) {
                const int c = wn * 32 + ni * 8 + gid;
                #pragma unroll
                for (int q = 0; q < 2; q++) {
                    const int kk = kc + tig + q * 4;
                    Bhi[ni][q] = WsH[kk * SSTR + c];
                    Blo[ni][q] = WsL[kk * SSTR + c];
                }
            }

            #pragma unroll
            for (int mi = 0; mi < 4; mi++)
                #pragma unroll
                for (int ni = 0; ni < 4; ni++) {
                    mma8(acc[mi][ni], Ahi[mi], Bhi[ni]);
                    mma8(acc[mi][ni], Ahi[mi], Blo[ni]);
                    mma8(acc[mi][ni], Alo[mi], Bhi[ni]);
                }
        }

        if (has_next) {
            // Store next tile to the OTHER buffer (not being read), then one sync.
            uint32_t* nAsH = psm + (buf ^ 1) * PBUF;
            uint32_t* nAsL = nAsH + PPLANE;
            uint32_t* nWsH = nAsH + 2 * PPLANE;
            uint32_t* nWsL = nAsH + 3 * PPLANE;
            const float av[8] = {pa0.x, pa0.y, pa0.z, pa0.w, pa1.x, pa1.y, pa1.z, pa1.w};
            const float wv[8] = {pw0.x, pw0.y, pw0.z, pw0.w, pw1.x, pw1.y, pw1.z, pw1.w};
            #pragma unroll
            for (int j = 0; j < 8; j++) {
                uint32_t h_, l_;
                split3(av[j], h_, l_);
                nAsH[(ldKg + j) * SSTR + ldRow] = h_; nAsL[(ldKg + j) * SSTR + ldRow] = l_;
                split3(wv[j], h_, l_);
                nWsH[(ldKg + j) * SSTR + ldRow] = h_; nWsL[(ldKg + j) * SSTR + ldRow] = l_;
            }
            __syncthreads();
            buf ^= 1;
        }
    }

    // Epilogue. Bias depends only on ni: hoist 4x float2 loads out of loops.
    float2 bfrag[4];
    #pragma unroll
    for (int ni = 0; ni < 4; ni++)
        bfrag[ni] = *reinterpret_cast<const float2*>(
            &bias[colBase + wn * 32 + ni * 8 + 2 * tig]);

    #pragma unroll
    for (int mi = 0; mi < 4; mi++) {
        #pragma unroll
        for (int half = 0; half < 2; half++) {
            const int gr = rowBase + wm * 64 + mi * 16 + gid + half * 8;
            const int s = gr >> 1;
            const int b = gr & 1;
            #pragma unroll
            for (int ni = 0; ni < 4; ni++) {
                const int gc = colBase + wn * 32 + ni * 8 + 2 * tig;
                float v0 = acc[mi][ni][half * 2 + 0] + bfrag[ni].x;
                float v1 = acc[mi][ni][half * 2 + 1] + bfrag[ni].y;

                if (rope) {
                    const int d = gc & 63;
                    const float c0 = cosT[(s << 6) + d];
                    const float s0 = sinT[(s << 6) + d];
                    const float c1 = cosT[(s << 6) + d + 1];
                    const float s1 = sinT[(s << 6) + d + 1];
                    const float xe = v0, xo = v1;
                    v0 = xe * c0 - xo * s0;
                    v1 = xo * c1 + xe * s1;
                }

                if (head_layout) {
                    const int h = gc >> 6;
                    const int dk = gc & 63;
                    *reinterpret_cast<float2*>(
                        &out[(((long)b * NHEAD + h) * S_LEN + s) * HDK + dk]) =
                        make_float2(v0, v1);
                } else {
                    *reinterpret_cast<float2*>(&out[(long)gr * DMODEL + gc]) =
                        make_float2(v0, v1);
                }
            }
        }
    }
}

// ---------------------------------------------------------------------------
// Tensor-core flash attention v4.1 (unchanged): QT=256, two m16 row groups
// per warp per B-fragment load; P relaid C->A via quad-local shfl;
// __launch_bounds__(256,1) licenses 255 regs (209 KB smem -> 1 CTA/SM).
// ---------------------------------------------------------------------------
#define QT 256
#define KT 64
#define FSTR 68
#define NKT (S_LEN / KT)
#define ATTN_SMEM_WORDS ((2 * QT + 4 * KT) * FSTR)
#define ATTN_SMEM_BYTES (ATTN_SMEM_WORDS * 4)

__global__ __launch_bounds__(256, 1) void attn_kernel(
    const float* __restrict__ Q, const float* __restrict__ K,
    const float* __restrict__ V, float* __restrict__ ctx)
{
    extern __shared__ uint32_t smu[];
    uint32_t* QsH = smu;                       // [QT][FSTR]
    uint32_t* QsL = QsH + QT * FSTR;
    uint32_t* KsH = QsL + QT * FSTR;           // [KT][FSTR]
    uint32_t* KsL = KsH + KT * FSTR;
    uint32_t* VtH = KsL + KT * FSTR;           // [64][FSTR] (dk x kcol)
    uint32_t* VtL = VtH + KT * FSTR;

    const int tid = threadIdx.x;
    const int lane = tid & 31;
    const int warp = tid >> 5;
    const int gid = lane >> 2;    // 0..7
    const int tig = lane & 3;     // 0..3
    const int wq0 = warp * 16;    // group0 row base; group1 = wq0 + 128

    const int bh = blockIdx.y;
    const int q0 = blockIdx.x * QT;

    const float* Qb = Q + (long)bh * S_LEN * HDK;
    const float* Kb = K + (long)bh * S_LEN * HDK;
    const float* Vb = V + (long)bh * S_LEN * HDK;

    const int kvr = tid & 63;            // 0..63
    const int kvc = (tid >> 6) * 16;     // 0,16,32,48

    // Load Q (one row per thread, split once) + K/V tile 0 (split)
    {
        const float4* qs = reinterpret_cast<const float4*>(&Qb[(q0 + tid) * HDK]);
        #pragma unroll
        for (int u = 0; u < 16; u++) {
            float4 v = qs[u];
            const int c = u * 4;
            uint32_t h_, l_;
            split3(v.x, h_, l_); QsH[tid * FSTR + c + 0] = h_; QsL[tid * FSTR + c + 0] = l_;
            split3(v.y, h_, l_); QsH[tid * FSTR + c + 1] = h_; QsL[tid * FSTR + c + 1] = l_;
            split3(v.z, h_, l_); QsH[tid * FSTR + c + 2] = h_; QsL[tid * FSTR + c + 2] = l_;
            split3(v.w, h_, l_); QsH[tid * FSTR + c + 3] = h_; QsL[tid * FSTR + c + 3] = l_;
        }
        const float4* ks = reinterpret_cast<const float4*>(&Kb[kvr * HDK + kvc]);
        const float4* vs = reinterpret_cast<const float4*>(&Vb[kvr * HDK + kvc]);
        #pragma unroll
        for (int u = 0; u < 4; u++) {
            float4 kv = ks[u];
            const int c = kvc + u * 4;
            uint32_t h_, l_;
            split3(kv.x, h_, l_); KsH[kvr * FSTR + c + 0] = h_; KsL[kvr * FSTR + c + 0] = l_;
            split3(kv.y, h_, l_); KsH[kvr * FSTR + c + 1] = h_; KsL[kvr * FSTR + c + 1] = l_;
            split3(kv.z, h_, l_); KsH[kvr * FSTR + c + 2] = h_; KsL[kvr * FSTR + c + 2] = l_;
            split3(kv.w, h_, l_); KsH[kvr * FSTR + c + 3] = h_; KsL[kvr * FSTR + c + 3] = l_;
        }
        #pragma unroll
        for (int u = 0; u < 4; u++) {
            float4 vv = vs[u];
            const int c = kvc + u * 4;
            uint32_t h_, l_;
            split3(vv.x, h_, l_); VtH[(c + 0) * FSTR + kvr] = h_; VtL[(c + 0) * FSTR + kvr] = l_;
            split3(vv.y, h_, l_); VtH[(c + 1) * FSTR + kvr] = h_; VtL[(c + 1) * FSTR + kvr] = l_;
            split3(vv.z, h_, l_); VtH[(c + 2) * FSTR + kvr] = h_; VtL[(c + 2) * FSTR + kvr] = l_;
            split3(vv.w, h_, l_); VtH[(c + 3) * FSTR + kvr] = h_; VtL[(c + 3) * FSTR + kvr] = l_;
        }
    }

    float o[2][8][4] = {};            // [group][dk-frag][creg]
    float mst[2][2], lst[2][2];       // [group][row-half]
    #pragma unroll
    for (int g = 0; g < 2; g++) {
        mst[g][0] = -1e30f; mst[g][1] = -1e30f;
        lst[g][0] = 0.0f;   lst[g][1] = 0.0f;
    }
    __syncthreads();

    float4 kr[4], vr[4];

    #pragma unroll 1
    for (int kt = 0; kt < NKT; kt++) {
        const int has_next = (kt + 1 < NKT);
        if (has_next) {
            const float4* ks = reinterpret_cast<const float4*>(&Kb[((kt + 1) * KT + kvr) * HDK + kvc]);
            const float4* vs = reinterpret_cast<const float4*>(&Vb[((kt + 1) * KT + kvr) * HDK + kvc]);
            #pragma unroll
            for (int u = 0; u < 4; u++) { kr[u] = ks[u]; vr[u] = vs[u]; }
        }

        // ---- S = Q K^T for BOTH groups; B fragments loaded once ----
        float sacc[2][8][4] = {};
        #pragma unroll
        for (int kc = 0; kc < 8; kc++) {
            uint32_t Ahi[2][4], Alo[2][4];
            #pragma unroll
            for (int g = 0; g < 2; g++)
                #pragma unroll
                for (int q = 0; q < 4; q++) {
                    const int kk = kc * 8 + tig + ((q >> 1) << 2);
                    const int rr = wq0 + g * 128 + gid + ((q & 1) << 3);
                    Ahi[g][q] = QsH[rr * FSTR + kk];
                    Alo[g][q] = QsL[rr * FSTR + kk];
                }
            #pragma unroll
            for (int nf = 0; nf < 8; nf++) {
                const int kcol = nf * 8 + gid;
                uint32_t Bhi[2], Blo[2];
                Bhi[0] = KsH[kcol * FSTR + kc * 8 + tig];
                Bhi[1] = KsH[kcol * FSTR + kc * 8 + tig + 4];
                Blo[0] = KsL[kcol * FSTR + kc * 8 + tig];
                Blo[1] = KsL[kcol * FSTR + kc * 8 + tig + 4];
                #pragma unroll
                for (int g = 0; g < 2; g++) {
                    mma8(sacc[g][nf], Ahi[g], Bhi);
                    mma8(sacc[g][nf], Ahi[g], Blo);
                    mma8(sacc[g][nf], Alo[g], Bhi);
                }
            }
        }

        // ---- Online softmax per group (C-frag layout: rows gid / gid+8) ----
        float alpha[2][2];
        #pragma unroll
        for (int g = 0; g < 2; g++) {
            float mx0 = -1e30f, mx1 = -1e30f;
            #pragma unroll
            for (int nf = 0; nf < 8; nf++) {
                #pragma unroll
                for (int c = 0; c < 4; c++) sacc[g][nf][c] *= 0.125f;
                mx0 = fmaxf(mx0, fmaxf(sacc[g][nf][0], sacc[g][nf][1]));
                mx1 = fmaxf(mx1, fmaxf(sacc[g][nf][2], sacc[g][nf][3]));
            }
            #pragma unroll
            for (int msk = 1; msk < 4; msk <<= 1) {
                mx0 = fmaxf(mx0, __shfl_xor_sync(0xffffffffu, mx0, msk));
                mx1 = fmaxf(mx1, __shfl_xor_sync(0xffffffffu, mx1, msk));
            }
            const float mn0 = fmaxf(mst[g][0], mx0);
            const float mn1 = fmaxf(mst[g][1], mx1);
            float sum0 = 0.0f, sum1 = 0.0f;
            #pragma unroll
            for (int nf = 0; nf < 8; nf++) {
                sacc[g][nf][0] = __expf(sacc[g][nf][0] - mn0);
                sacc[g][nf][1] = __expf(sacc[g][nf][1] - mn0);
                sacc[g][nf][2] = __expf(sacc[g][nf][2] - mn1);
                sacc[g][nf][3] = __expf(sacc[g][nf][3] - mn1);
                sum0 += sacc[g][nf][0] + sacc[g][nf][1];
                sum1 += sacc[g][nf][2] + sacc[g][nf][3];
            }
            #pragma unroll
            for (int msk = 1; msk < 4; msk <<= 1) {
                sum0 += __shfl_xor_sync(0xffffffffu, sum0, msk);
                sum1 += __shfl_xor_sync(0xffffffffu, sum1, msk);
            }
            alpha[g][0] = __expf(mst[g][0] - mn0);
            alpha[g][1] = __expf(mst[g][1] - mn1);
            lst[g][0] = lst[g][0] * alpha[g][0] + sum0;  mst[g][0] = mn0;
            lst[g][1] = lst[g][1] * alpha[g][1] + sum1;  mst[g][1] = mn1;
        }

        // ---- Rescale O ----
        #pragma unroll
        for (int g = 0; g < 2; g++)
            #pragma unroll
            for (int nf = 0; nf < 8; nf++) {
                o[g][nf][0] *= alpha[g][0]; o[g][nf][1] *= alpha[g][0];
                o[g][nf][2] *= alpha[g][1]; o[g][nf][3] *= alpha[g][1];
            }

        // ---- O += P @ V. A-frags from sacc via quad-local shfl relayout:
        //      col j = kc*8+tig lives in lane (4*gid + (tig>>1)) as c[tig&1]
        //      (row gid) / c[2+(tig&1)] (row gid+8); col j+4 in lane +2. ----
        const int s0 = (lane & ~3) | (tig >> 1);
        const int s2 = s0 + 2;
        const bool esel = (tig & 1);
        #pragma unroll
        for (int kc = 0; kc < 8; kc++) {
            uint32_t Phi[2][4], Plo[2][4];
            #pragma unroll
            for (int g = 0; g < 2; g++) {
                const float c0 = sacc[g][kc][0];
                const float c1 = sacc[g][kc][1];
                const float c2 = sacc[g][kc][2];
                const float c3 = sacc[g][kc][3];
                const float v00 = __shfl_sync(0xffffffffu, c0, s0);
                const float v10 = __shfl_sync(0xffffffffu, c1, s0);
                const float v20 = __shfl_sync(0xffffffffu, c2, s0);
                const float v30 = __shfl_sync(0xffffffffu, c3, s0);
                const float v02 = __shfl_sync(0xffffffffu, c0, s2);
                const float v12 = __shfl_sync(0xffffffffu, c1, s2);
                const float v22 = __shfl_sync(0xffffffffu, c2, s2);
                const float v32 = __shfl_sync(0xffffffffu, c3, s2);
                const float a0 = esel ? v10 : v00;   // P[gid][kc*8+tig]
                const float a1 = esel ? v30 : v20;   // P[gid+8][kc*8+tig]
                const float a2 = esel ? v12 : v02;   // P[gid][kc*8+tig+4]
                const float a3 = esel ? v32 : v22;   // P[gid+8][kc*8+tig+4]
                split3(a0, Phi[g][0], Plo[g][0]);
                split3(a1, Phi[g][1], Plo[g][1]);
                split3(a2, Phi[g][2], Plo[g][2]);
                split3(a3, Phi[g][3], Plo[g][3]);
            }
            #pragma unroll
            for (int nf = 0; nf < 8; nf++) {
                const int dk = nf * 8 + gid;
                uint32_t Bhi[2], Blo[2];
                Bhi[0] = VtH[dk * FSTR + kc * 8 + tig];
                Bhi[1] = VtH[dk * FSTR + kc * 8 + tig + 4];
                Blo[0] = VtL[dk * FSTR + kc * 8 + tig];
                Blo[1] = VtL[dk * FSTR + kc * 8 + tig + 4];
                #pragma unroll
                for (int g = 0; g < 2; g++) {
                    mma8(o[g][nf], Phi[g], Bhi);
                    mma8(o[g][nf], Phi[g], Blo);
                    mma8(o[g][nf], Plo[g], Bhi);
                }
            }
        }
        __syncthreads();   // done reading Ks/Vt

        if (has_next) {
            #pragma unroll
            for (int u = 0; u < 4; u++) {
                const int c = kvc + u * 4;
                uint32_t h_, l_;
                split3(kr[u].x, h_, l_); KsH[kvr * FSTR + c + 0] = h_; KsL[kvr * FSTR + c + 0] = l_;
                split3(kr[u].y, h_, l_); KsH[kvr * FSTR + c + 1] = h_; KsL[kvr * FSTR + c + 1] = l_;
                split3(kr[u].z, h_, l_); KsH[kvr * FSTR + c + 2] = h_; KsL[kvr * FSTR + c + 2] = l_;
                split3(kr[u].w, h_, l_); KsH[kvr * FSTR + c + 3] = h_; KsL[kvr * FSTR + c + 3] = l_;
            }
            #pragma unroll
            for (int u = 0; u < 4; u++) {
                const int c = kvc + u * 4;
                uint32_t h_, l_;
                split3(vr[u].x, h_, l_); VtH[(c + 0) * FSTR + kvr] = h_; VtL[(c + 0) * FSTR + kvr] = l_;
                split3(vr[u].y, h_, l_); VtH[(c + 1) * FSTR + kvr] = h_; VtL[(c + 1) * FSTR + kvr] = l_;
                split3(vr[u].z, h_, l_); VtH[(c + 2) * FSTR + kvr] = h_; VtL[(c + 2) * FSTR + kvr] = l_;
                split3(vr[u].w, h_, l_); VtH[(c + 3) * FSTR + kvr] = h_; VtL[(c + 3) * FSTR + kvr] = l_;
            }
            __syncthreads();
        }
    }

    // ---- Finalize: ctx[s, b, h*64 + d] = o / l ----
    const int bb = bh / NHEAD;
    const int hh = bh % NHEAD;
    #pragma unroll
    for (int g = 0; g < 2; g++) {
        const float il0 = 1.0f / lst[g][0];
        const float il1 = 1.0f / lst[g][1];
        #pragma unroll
        for (int half = 0; half < 2; half++) {
            const int s = q0 + wq0 + g * 128 + gid + half * 8;
            const float il = half ? il1 : il0;
            #pragma unroll
            for (int nf = 0; nf < 8; nf++) {
                const int d = nf * 8 + 2 * tig;
                *reinterpret_cast<float2*>(
                    &ctx[((long)s * BATCH + bb) * DMODEL + hh * HDK + d]) =
                    make_float2(o[g][nf][half * 2 + 0] * il, o[g][nf][half * 2 + 1] * il);
            }
        }
    }
}

// ---------------------------------------------------------------------------
extern "C" void kernel_launch(void* const* d_in, const int* in_sizes, int n_in,
                              void* d_out, int out_size)
{
    const float* query = (const float*)d_in[0];
    const float* key_  = (const float*)d_in[1];
    const float* value = (const float*)d_in[2];
    const float* wq = (const float*)d_in[3];
    const float* bq = (const float*)d_in[4];
    const float* wk = (const float*)d_in[5];
    const float* bk = (const float*)d_in[6];
    const float* wv = (const float*)d_in[7];
    const float* bv = (const float*)d_in[8];
    const float* wo = (const float*)d_in[9];
    const float* bo = (const float*)d_in[10];
    float* out = (float*)d_out;

    float *gq, *gk, *gv, *gctx, *gcos, *gsin;
    cudaGetSymbolAddress((void**)&gq, g_q);
    cudaGetSymbolAddress((void**)&gk, g_k);
    cudaGetSymbolAddress((void**)&gv, g_v);
    cudaGetSymbolAddress((void**)&gctx, g_ctx);
    cudaGetSymbolAddress((void**)&gcos, g_cos);
    cudaGetSymbolAddress((void**)&gsin, g_sin);

    cudaFuncSetAttribute(attn_kernel, cudaFuncAttributeMaxDynamicSharedMemorySize,
                         ATTN_SMEM_BYTES);
    cudaFuncSetAttribute(proj_kernel, cudaFuncAttributeMaxDynamicSharedMemorySize,
                         PROJ_SMEM_BYTES);

    dim3 blk(256);

    rope_table_kernel<<<(S_LEN * HDK) / 256, blk>>>(gcos, gsin);

    dim3 gqkv(DMODEL / 128, NROWS / 128, 3);
    proj_kernel<<<gqkv, blk, PROJ_SMEM_BYTES>>>(query, key_, value,
                               wq, wk, wv,
                               bq, bk, bv,
                               gq, gk, gv,
                               gcos, gsin,
                               /*rope_mask=*/0b011, /*head_layout=*/1);

    dim3 gattn(S_LEN / QT, BATCH * NHEAD);
    attn_kernel<<<gattn, blk, ATTN_SMEM_BYTES>>>(gq, gk, gv, gctx);

    dim3 gout(DMODEL / 128, NROWS / 128, 1);
    proj_kernel<<<gout, blk, PROJ_SMEM_BYTES>>>(gctx, gctx, gctx,
                               wo, wo, wo,
                               bo, bo, bo,
                               out, out, out,
                               gcos, gsin,
                               /*rope_mask=*/0, /*head_layout=*/0);
}